// round 4
// baseline (speedup 1.0000x reference)
#include <cuda_runtime.h>
#include <math.h>
#include <stdint.h>

#define BATCH 1024
#define C0 512
#define C1 1024
#define K0 100
#define K1 50
#define BPB 8     /* batch rows per head block */

#define POOL_THREADS 128
#define CHUNK_FLOATS (POOL_THREADS * 49)      /* 6272 floats = 25088 B  */
#define CHUNK_BYTES  (CHUNK_FLOATS * 4)
#define NB_POOL0     ((BATCH * C0) / 32)      /* 16384 chunks for feat0 */
#define NB_POOL1     ((BATCH * C1) / 128)     /* 8192 chunks for feat1  */
#define NCHUNKS      (NB_POOL0 + NB_POOL1)    /* 24576 */
#define POOL_GRID    592                       /* 4 blocks/SM x 148 SM  */

#define NHB (2 * (BATCH / BPB))               /* 256 head blocks */
#define SMEM_DYN (2 * CHUNK_BYTES + 128)

// ---------------- scratch (device globals; no allocation) ----------------
__device__ float g_pooled0[BATCH * C0];
__device__ float g_pooled1[BATCH * C1];
__device__ float g_pnll[NHB];
__device__ float g_pws [NHB];
__device__ int   g_pool_done;   // zero-init; reset each run by last head block
__device__ int   g_head_done;   // zero-init; reset each run by last head block

// ---------------- PTX helpers ---------------------------------------------
__device__ __forceinline__ uint32_t smem_u32(const void* p) {
    uint32_t a;
    asm("{ .reg .u64 t; cvta.to.shared.u64 t, %1; cvt.u32.u64 %0, t; }"
        : "=r"(a) : "l"(p));
    return a;
}
#define MBAR_INIT(a, c) \
    asm volatile("mbarrier.init.shared.b64 [%0], %1;" :: "r"(a), "r"(c) : "memory")
#define MBAR_EXPECT_TX(a, b) \
    asm volatile("mbarrier.arrive.expect_tx.shared.b64 _, [%0], %1;" :: "r"(a), "r"(b) : "memory")
#define BULK_G2S(dst, src, bytes, mbar) \
    asm volatile("cp.async.bulk.shared::cluster.global.mbarrier::complete_tx::bytes " \
                 "[%0], [%1], %2, [%3];" \
                 :: "r"(dst), "l"(src), "r"(bytes), "r"(mbar) : "memory")
__device__ __forceinline__ void mbar_wait(uint32_t mbar, uint32_t parity) {
    asm volatile(
        "{\n\t.reg .pred P;\n\t"
        "WL_%=:\n\t"
        "mbarrier.try_wait.parity.acquire.cta.shared::cta.b64 P, [%0], %1, 0x989680;\n\t"
        "@P bra.uni WD_%=;\n\t"
        "bra.uni WL_%=;\n\t"
        "WD_%=:\n\t}"
        :: "r"(mbar), "r"(parity) : "memory");
}
#define FMA2(acc, a, b) \
    asm("fma.rn.f32x2 %0, %1, %2, %0;" : "+l"(acc) : "l"(a), "l"(b))

// ---------------- fused persistent kernel ----------------------------------
__global__ void __launch_bounds__(POOL_THREADS, 4) fused_kernel(
        const float* __restrict__ feat0, const float* __restrict__ feat1,
        const float* __restrict__ W0, const float* __restrict__ b0,
        const float* __restrict__ W1, const float* __restrict__ b1,
        const int*   __restrict__ lut0, const int* __restrict__ lut1,
        const float* __restrict__ cw0, const float* __restrict__ cw1,
        const int*   __restrict__ target, float* __restrict__ out) {
    extern __shared__ __align__(128) char smem[];
    const int t   = threadIdx.x;
    const int bid = blockIdx.x;

    // ======================= POOL PHASE =======================
    {
        float* buf[2] = { (float*)smem, (float*)(smem + CHUNK_BYTES) };
        uint32_t mbar[2] = { smem_u32(smem + 2 * CHUNK_BYTES),
                             smem_u32(smem + 2 * CHUNK_BYTES + 8) };

        if (t == 0) { MBAR_INIT(mbar[0], 1); MBAR_INIT(mbar[1], 1); }
        __syncthreads();

        auto issue = [&](int chunk, int bb) {
            const char* src = (chunk < NB_POOL0)
                ? (const char*)feat0 + (size_t)chunk * CHUNK_BYTES
                : (const char*)feat1 + (size_t)(chunk - NB_POOL0) * CHUNK_BYTES;
            MBAR_EXPECT_TX(mbar[bb], CHUNK_BYTES);
            BULK_G2S(smem_u32(buf[bb]), src, CHUNK_BYTES, mbar[bb]);
        };

        if (t == 0) {
            if (bid < NCHUNKS)             issue(bid, 0);
            if (bid + POOL_GRID < NCHUNKS) issue(bid + POOL_GRID, 1);
        }

        int parity[2] = { 0, 0 };
        int it = 0;
        for (int chunk = bid; chunk < NCHUNKS; chunk += POOL_GRID, it++) {
            const int bb = it & 1;
            mbar_wait(mbar[bb], parity[bb]);
            parity[bb] ^= 1;

            const float* p = buf[bb] + 49 * t;   // odd stride: conflict-free
            float s0 = 0.f, s1 = 0.f, s2 = 0.f, s3 = 0.f;
            #pragma unroll
            for (int j = 0; j < 48; j += 4) {
                s0 += p[j]; s1 += p[j + 1]; s2 += p[j + 2]; s3 += p[j + 3];
            }
            float s = (s0 + s1) + (s2 + s3) + p[48];

            if (chunk < NB_POOL0) {
                s += __shfl_down_sync(0xffffffffu, s, 2);
                s += __shfl_down_sync(0xffffffffu, s, 1);
                if ((t & 3) == 0)
                    g_pooled0[chunk * 32 + (t >> 2)] = s * (1.0f / 196.0f);
            } else {
                g_pooled1[(chunk - NB_POOL0) * 128 + t] = s * (1.0f / 49.0f);
            }

            __syncthreads();
            if (t == 0 && chunk + 2 * POOL_GRID < NCHUNKS)
                issue(chunk + 2 * POOL_GRID, bb);
        }
    }

    // ======================= GRID GATE =======================
    __threadfence();          // every thread's pooled stores -> gpu scope
    __syncthreads();
    if (t == 0) atomicAdd(&g_pool_done, 1);
    if (bid >= NHB) return;   // non-head blocks retire

    if (t == 0) {
        while (atomicAdd(&g_pool_done, 0) < POOL_GRID) { }
    }
    __syncthreads();
    __threadfence();          // acquire side

    // ======================= HEAD PHASE =======================
    float* sp   = (float*)smem;                       // BPB*C1 floats (32 KB)
    float* slog = (float*)(smem + BPB * C1 * 4);      // BPB*128 floats (4 KB)
    float* s_nll = slog + BPB * 128;                  // BPB
    float* s_ws  = s_nll + BPB;                       // BPB

    const int  nb0   = BATCH / BPB;
    const bool head  = (bid >= nb0);
    const int  bbase = (head ? (bid - nb0) : bid) * BPB;

    const int    C      = head ? C1 : C0;
    const int    K      = head ? K1 : K0;
    const float* pooled = head ? g_pooled1 : g_pooled0;
    const float* W      = head ? W1 : W0;
    const float* bias   = head ? b1 : b0;
    const int*   lut    = head ? lut1 : lut0;
    const float* cw     = head ? cw1 : cw0;

    {   // stage BPB pooled rows into smem
        const float4* src = reinterpret_cast<const float4*>(pooled + (size_t)bbase * C);
        float4* dst = reinterpret_cast<float4*>(sp);
        const int n4 = (BPB * C) >> 2;
        for (int i = t; i < n4; i += 128) dst[i] = src[i];
    }
    __syncthreads();

    float logit[BPB];
    if (t < K) {
        uint64_t accA[BPB], accB[BPB];
        #pragma unroll
        for (int j = 0; j < BPB; j++) { accA[j] = 0ull; accB[j] = 0ull; }
        const ulonglong2* w2 = reinterpret_cast<const ulonglong2*>(W + (size_t)t * C);
        const int C4 = C >> 2;
        for (int c4 = 0; c4 < C4; c4++) {
            ulonglong2 wv = __ldg(w2 + c4);
            #pragma unroll
            for (int j = 0; j < BPB; j++) {
                ulonglong2 pv = *reinterpret_cast<const ulonglong2*>(&sp[j * C + (c4 << 2)]);
                FMA2(accA[j], pv.x, wv.x);
                FMA2(accB[j], pv.y, wv.y);
            }
        }
        float bv = bias[t];
        #pragma unroll
        for (int j = 0; j < BPB; j++) {
            float ax = __uint_as_float((uint32_t)accA[j]);
            float ay = __uint_as_float((uint32_t)(accA[j] >> 32));
            float bx = __uint_as_float((uint32_t)accB[j]);
            float by = __uint_as_float((uint32_t)(accB[j] >> 32));
            logit[j] = (ax + ay) + (bx + by) + bv;
        }
    }
    #pragma unroll
    for (int j = 0; j < BPB; j++)
        slog[j * 128 + t] = (t < K) ? logit[j] : -INFINITY;
    __syncthreads();

    const int warp = t >> 5, lane = t & 31;
    for (int j = warp; j < BPB; j += 4) {
        float v0 = slog[j * 128 + lane];
        float v1 = slog[j * 128 + lane + 32];
        float v2 = slog[j * 128 + lane + 64];
        float v3 = slog[j * 128 + lane + 96];
        float mx = fmaxf(fmaxf(v0, v1), fmaxf(v2, v3));
        #pragma unroll
        for (int o = 16; o > 0; o >>= 1)
            mx = fmaxf(mx, __shfl_xor_sync(0xffffffffu, mx, o));
        float se = expf(v0 - mx) + expf(v1 - mx) + expf(v2 - mx) + expf(v3 - mx);
        #pragma unroll
        for (int o = 16; o > 0; o >>= 1)
            se += __shfl_xor_sync(0xffffffffu, se, o);
        if (lane == 0) {
            float lse  = mx + logf(se);
            int   bidx = bbase + j;
            int   tc   = lut[target[bidx]];
            float nll  = lse - slog[j * 128 + tc];
            float w    = cw[tc];
            s_nll[j] = w * nll;
            s_ws [j] = w;
        }
    }
    __syncthreads();

    __shared__ int s_last;
    if (t == 0) {
        float pn = 0.f, pw = 0.f;
        #pragma unroll
        for (int j = 0; j < BPB; j++) { pn += s_nll[j]; pw += s_ws[j]; }
        g_pnll[bid] = pn;
        g_pws [bid] = pw;
        __threadfence();
        s_last = (atomicAdd(&g_head_done, 1) == NHB - 1);
    }
    __syncthreads();

    // ======================= FINALIZE (last head block) =======================
    if (s_last) {
        __threadfence();
        float n0 = g_pnll[t],        w0 = g_pws[t];
        float n1 = g_pnll[128 + t],  w1 = g_pws[128 + t];
        #pragma unroll
        for (int o = 16; o > 0; o >>= 1) {
            n0 += __shfl_down_sync(0xffffffffu, n0, o);
            w0 += __shfl_down_sync(0xffffffffu, w0, o);
            n1 += __shfl_down_sync(0xffffffffu, n1, o);
            w1 += __shfl_down_sync(0xffffffffu, w1, o);
        }
        if (lane == 0) {
            slog[warp * 4 + 0] = n0; slog[warp * 4 + 1] = w0;
            slog[warp * 4 + 2] = n1; slog[warp * 4 + 3] = w1;
        }
        __syncthreads();
        if (t == 0) {
            float a = 0.f, b = 0.f, c = 0.f, d = 0.f;
            #pragma unroll
            for (int w = 0; w < 4; w++) {
                a += slog[w * 4 + 0]; b += slog[w * 4 + 1];
                c += slog[w * 4 + 2]; d += slog[w * 4 + 3];
            }
            out[0] = a / b + c / d;
            // reset gates for next graph replay (all readers have passed)
            g_pool_done = 0;
            g_head_done = 0;
        }
    }
}

// ---------------- launch ----------------------------------------------------
extern "C" void kernel_launch(void* const* d_in, const int* in_sizes, int n_in,
                              void* d_out, int out_size) {
    const float* feat0  = (const float*)d_in[0];
    const float* feat1  = (const float*)d_in[1];
    const float* W0     = (const float*)d_in[2];
    const float* b0     = (const float*)d_in[3];
    const float* W1     = (const float*)d_in[4];
    const float* b1     = (const float*)d_in[5];
    const int*   lut0   = (const int*)  d_in[6];
    const int*   lut1   = (const int*)  d_in[7];
    const float* cw0    = (const float*)d_in[8];
    const float* cw1    = (const float*)d_in[9];
    const int*   target = (const int*)  d_in[10];

    static bool attr_set = false;
    if (!attr_set) {
        cudaFuncSetAttribute(fused_kernel,
                             cudaFuncAttributeMaxDynamicSharedMemorySize,
                             SMEM_DYN);
        attr_set = true;
    }

    fused_kernel<<<POOL_GRID, POOL_THREADS, SMEM_DYN>>>(
        feat0, feat1, W0, b0, W1, b1, lut0, lut1, cw0, cw1, target,
        (float*)d_out);
}